// round 6
// baseline (speedup 1.0000x reference)
#include <cuda_runtime.h>
#include <cuda_bf16.h>

// SSIM loss, round 6: packed fp32 math via PTX fma.rn.f32x2.
// Field pairs {p,t} and {(p+t)^2,(p-t)^2} share Gaussian weights, so each
// packed FFMA2 does 2 lane-FMAs -> FMA issue slots halved vs round 5.
// hb is stored field-pair interleaved (float2) so phase H LDS.128 yields
// packed operands directly.

#define TW 64
#define TH 64
#define RAD 5
#define INW 74          // TW + 2*RAD
#define HBW2 76         // row stride in float2 units (608B, 16B-aligned)
#define GROUPS 4        // row groups of 16
#define NITEMS (INW * GROUPS)   // 296
#define HW 512
#define PLANE_ELEMS (512 * 512)
#define NBLOCKS 3072

// Gaussian(sigma=1.5, window=11), normalized.
#define W0 0.00102838f
#define W1 0.00759877f
#define W2 0.03600077f
#define W3 0.10936070f
#define W4 0.21300554f
#define W5 0.26601173f

typedef unsigned long long ull;

__device__ float g_partials[NBLOCKS];
__device__ unsigned int g_counter = 0;

__device__ __forceinline__ ull f2pack(float lo, float hi) {
    ull d;
    asm("mov.b64 %0, {%1, %2};" : "=l"(d) : "f"(lo), "f"(hi));
    return d;
}
__device__ __forceinline__ void f2unpack(float& lo, float& hi, ull v) {
    asm("mov.b64 {%0, %1}, %2;" : "=f"(lo), "=f"(hi) : "l"(v));
}
__device__ __forceinline__ ull fma2(ull a, ull b, ull c) {
    ull d;
    asm("fma.rn.f32x2 %0, %1, %2, %3;" : "=l"(d) : "l"(a), "l"(b), "l"(c));
    return d;
}

// Vertical 11-tap conv, one column x 16 output rows per item, transposed-FIR
// ring of packed accumulators. hb01 gets {conv p, conv t}, hb23 gets
// {conv (p+t)^2, conv (p-t)^2}.
template<bool INTERIOR>
__device__ __forceinline__ void ssim_phase_v(
    const float* __restrict__ pp, const float* __restrict__ tt,
    int x0, int y0, int tid, ull* __restrict__ hb01, ull* __restrict__ hb23,
    const ull* __restrict__ Wb)
{
    for (int item = tid; item < NITEMS; item += 256) {
        int g = item / INW;
        int c = item - g * INW;
        int gx = x0 - RAD + c;
        int gybase = y0 + 16 * g - RAD;
        bool xok = INTERIOR || ((gx >= 0) && (gx < HW));
        const float* __restrict__ prow = pp + (size_t)gybase * HW + gx;
        const float* __restrict__ trow = tt + (size_t)gybase * HW + gx;

        ull a01[11], a23[11];
#pragma unroll
        for (int s = 0; s < 11; s++) { a01[s] = 0ull; a23[s] = 0ull; }

#pragma unroll
        for (int rr = 0; rr < 26; rr++) {
            float p, t;
            if (INTERIOR) {
                p = __ldg(prow + rr * HW);
                t = __ldg(trow + rr * HW);
            } else {
                int gy = gybase + rr;
                p = 0.f; t = 0.f;
                if (xok && gy >= 0 && gy < HW) {
                    p = __ldg(prow + rr * HW);
                    t = __ldg(trow + rr * HW);
                }
            }
            float sv = p + t;
            float dv = p - t;
            ull pt = f2pack(p, t);
            ull sd = f2pack(sv * sv, dv * dv);
#pragma unroll
            for (int j = 0; j < 16; j++) {
                int k = rr - j;
                if (k >= 0 && k <= 10) {
                    int slot = j % 11;
                    a01[slot] = fma2(Wb[k], pt, a01[slot]);
                    a23[slot] = fma2(Wb[k], sd, a23[slot]);
                }
            }
            if (rr >= 10) {
                int j = rr - 10;
                int slot = j % 11;
                int row = 16 * g + j;
                hb01[row * HBW2 + c] = a01[slot];  a01[slot] = 0ull;
                hb23[row * HBW2 + c] = a23[slot];  a23[slot] = 0ull;
            }
        }
    }
}

__global__ __launch_bounds__(256, 2) void ssim_main_kernel(
    const float* __restrict__ pred,
    const float* __restrict__ target,
    float* __restrict__ out,
    float inv_count)
{
    extern __shared__ __align__(16) ull smem_raw[];
    ull* hb01 = smem_raw;                       // [64][76] u64 = 38912 B
    ull* hb23 = smem_raw + TH * HBW2;           // [64][76] u64 = 38912 B
    __shared__ float red[8];
    __shared__ bool s_last;

    const int tid = threadIdx.x;
    const int x0 = blockIdx.x * TW;
    const int y0 = blockIdx.y * TH;
    const size_t plane_off = (size_t)blockIdx.z * PLANE_ELEMS;
    const float* __restrict__ pp = pred + plane_off;
    const float* __restrict__ tt = target + plane_off;

    // Broadcast weight pairs {W[k], W[k]} (symmetric window).
    ull Wb[11];
    Wb[0]  = f2pack(W0, W0);  Wb[1]  = f2pack(W1, W1);
    Wb[2]  = f2pack(W2, W2);  Wb[3]  = f2pack(W3, W3);
    Wb[4]  = f2pack(W4, W4);  Wb[5]  = f2pack(W5, W5);
    Wb[6]  = Wb[4]; Wb[7] = Wb[3]; Wb[8] = Wb[2]; Wb[9] = Wb[1]; Wb[10] = Wb[0];

    // ---- Phase V ----
    const bool interior =
        (x0 >= RAD) && (x0 + TW + RAD <= HW) && (y0 >= RAD) && (y0 + TH + RAD <= HW);
    if (interior) ssim_phase_v<true >(pp, tt, x0, y0, tid, hb01, hb23, Wb);
    else          ssim_phase_v<false>(pp, tt, x0, y0, tid, hb01, hb23, Wb);
    __syncthreads();

    // ---- Phase H: 4 items/thread; item = 4 consecutive x in one row ----
    const float C1 = 0.0001f;
    const float C2 = 0.0009f;
    float local = 0.f;

#pragma unroll
    for (int it = 0; it < 4; it++) {
        int h = tid + 256 * it;
        int r = h >> 4;
        int cg = (h & 15) << 2;
        const ull* rb01 = hb01 + r * HBW2 + cg;
        const ull* rb23 = hb23 + r * HBW2 + cg;

        float mu1[4], mu2[4], css[4], cdd[4];

        // Batch 1: fields {p, t} -> mu1, mu2
        {
            ull v[16];
#pragma unroll
            for (int q = 0; q < 8; q++) {
                ulonglong2 u = *(const ulonglong2*)(rb01 + 2 * q);
                v[2 * q] = u.x; v[2 * q + 1] = u.y;
            }
            ull acc[4] = {0ull, 0ull, 0ull, 0ull};
#pragma unroll
            for (int i = 0; i < 14; i++) {
#pragma unroll
                for (int j = 0; j < 4; j++) {
                    int k = i - j;
                    if (k >= 0 && k <= 10)
                        acc[j] = fma2(Wb[k], v[i], acc[j]);
                }
            }
#pragma unroll
            for (int j = 0; j < 4; j++) f2unpack(mu1[j], mu2[j], acc[j]);
        }
        // Batch 2: fields {(p+t)^2, (p-t)^2} -> css, cdd
        {
            ull v[16];
#pragma unroll
            for (int q = 0; q < 8; q++) {
                ulonglong2 u = *(const ulonglong2*)(rb23 + 2 * q);
                v[2 * q] = u.x; v[2 * q + 1] = u.y;
            }
            ull acc[4] = {0ull, 0ull, 0ull, 0ull};
#pragma unroll
            for (int i = 0; i < 14; i++) {
#pragma unroll
                for (int j = 0; j < 4; j++) {
                    int k = i - j;
                    if (k >= 0 && k <= 10)
                        acc[j] = fma2(Wb[k], v[i], acc[j]);
                }
            }
#pragma unroll
            for (int j = 0; j < 4; j++) f2unpack(css[j], cdd[j], acc[j]);
        }

#pragma unroll
        for (int j = 0; j < 4; j++) {
            float m1 = mu1[j], m2 = mu2[j];
            float m1s = m1 * m1;
            float m2s = m2 * m2;
            float m12 = m1 * m2;
            float ept   = 0.25f * (css[j] - cdd[j]);   // E[pt]
            float epptt = 0.5f  * (css[j] + cdd[j]);   // E[pp]+E[tt]
            float s12  = ept - m12;
            float ssum = epptt - m1s - m2s;            // sigma1^2 + sigma2^2
            float num = (2.0f * m12 + C1) * (2.0f * s12 + C2);
            float den = (m1s + m2s + C1) * (ssum + C2);
            local += __fdividef(num, den);
        }
    }

    // ---- Block reduction -> partial; last block reduces globally ----
#pragma unroll
    for (int off = 16; off > 0; off >>= 1)
        local += __shfl_down_sync(0xffffffffu, local, off);
    if ((tid & 31) == 0) red[tid >> 5] = local;
    __syncthreads();
    if (tid == 0) {
        float v = red[0] + red[1] + red[2] + red[3]
                + red[4] + red[5] + red[6] + red[7];
        int bid = (blockIdx.z * gridDim.y + blockIdx.y) * gridDim.x + blockIdx.x;
        g_partials[bid] = v;
        __threadfence();
        unsigned int n = atomicAdd(&g_counter, 1u);
        s_last = (n == NBLOCKS - 1u);
    }
    __syncthreads();

    if (s_last) {
        __threadfence();
        __shared__ double dred[8];
        const float4* __restrict__ p4 = (const float4*)g_partials;
        double acc = 0.0;
#pragma unroll
        for (int i = 0; i < NBLOCKS / 4 / 256; i++) {    // 3 iterations
            float4 v = p4[i * 256 + tid];
            acc += (double)v.x + (double)v.y + (double)v.z + (double)v.w;
        }
#pragma unroll
        for (int off = 16; off > 0; off >>= 1)
            acc += __shfl_down_sync(0xffffffffu, acc, off);
        if ((tid & 31) == 0) dred[tid >> 5] = acc;
        __syncthreads();
        if (tid == 0) {
            double s = dred[0] + dred[1] + dred[2] + dred[3]
                     + dred[4] + dred[5] + dred[6] + dred[7];
            out[0] = 1.0f - (float)(s * (double)inv_count);
            g_counter = 0;   // reset for next graph replay
        }
    }
}

extern "C" void kernel_launch(void* const* d_in, const int* in_sizes, int n_in,
                              void* d_out, int out_size) {
    const float* pred = (const float*)d_in[0];
    const float* target = (const float*)d_in[1];
    float* out = (float*)d_out;

    const int total = in_sizes[0];                 // N*C*H*W
    const int nplanes = total / PLANE_ELEMS;       // 48

    const size_t smem = sizeof(ull) * 2 * TH * HBW2;   // 77824 B
    cudaFuncSetAttribute(ssim_main_kernel,
                         cudaFuncAttributeMaxDynamicSharedMemorySize, (int)smem);

    dim3 grid(HW / TW, HW / TH, nplanes);          // (8, 8, 48) = 3072 blocks
    ssim_main_kernel<<<grid, 256, smem>>>(pred, target, out, 1.0f / (float)total);
}

// round 7
// speedup vs baseline: 1.0350x; 1.0350x over previous
#include <cuda_runtime.h>
#include <cuda_bf16.h>

// SSIM loss, round 7: 256x16 strips (V items 266 ~ 256 threads), 4-row LDG
// prefetch pipeline in phase V, packed f32x2 math, 2 blocks/SM.

#define TW 256
#define TH 16
#define RAD 5
#define INW 266         // TW + 2*RAD
#define HBW2 268        // row stride in u64 units (2144B, 16B-aligned)
#define HW 512
#define PLANE_ELEMS (512 * 512)
#define NBLOCKS 3072

// Gaussian(sigma=1.5, window=11), normalized.
#define W0 0.00102838f
#define W1 0.00759877f
#define W2 0.03600077f
#define W3 0.10936070f
#define W4 0.21300554f
#define W5 0.26601173f

typedef unsigned long long ull;

__device__ float g_partials[NBLOCKS];
__device__ unsigned int g_counter = 0;

__device__ __forceinline__ ull f2pack(float lo, float hi) {
    ull d;
    asm("mov.b64 %0, {%1, %2};" : "=l"(d) : "f"(lo), "f"(hi));
    return d;
}
__device__ __forceinline__ void f2unpack(float& lo, float& hi, ull v) {
    asm("mov.b64 {%0, %1}, %2;" : "=f"(lo), "=f"(hi) : "l"(v));
}
__device__ __forceinline__ ull fma2(ull a, ull b, ull c) {
    ull d;
    asm("fma.rn.f32x2 %0, %1, %2, %3;" : "=l"(d) : "l"(a), "l"(b), "l"(c));
    return d;
}

// Vertical 11-tap conv of packed {p,t} and {(p+t)^2,(p-t)^2}, one column,
// 16 output rows, transposed-FIR ring, 4-row LDG prefetch pipeline.
template<bool INTERIOR>
__device__ __forceinline__ void ssim_phase_v(
    const float* __restrict__ pp, const float* __restrict__ tt,
    int x0, int y0, int tid, ull* __restrict__ hb01, ull* __restrict__ hb23,
    const ull* __restrict__ Wb)
{
    for (int c = tid; c < INW; c += 256) {
        int gx = x0 - RAD + c;
        int gybase = y0 - RAD;
        bool xok = INTERIOR || ((gx >= 0) && (gx < HW));
        const float* __restrict__ prow = pp + (size_t)gybase * HW + gx;
        const float* __restrict__ trow = tt + (size_t)gybase * HW + gx;

        ull a01[11], a23[11];
#pragma unroll
        for (int s = 0; s < 11; s++) { a01[s] = 0ull; a23[s] = 0ull; }

        float pb[4], tb[4];
#pragma unroll
        for (int i = 0; i < 4; i++) {
            if (INTERIOR) {
                pb[i] = __ldg(prow + i * HW);
                tb[i] = __ldg(trow + i * HW);
            } else {
                int gy = gybase + i;
                pb[i] = 0.f; tb[i] = 0.f;
                if (xok && gy >= 0 && gy < HW) {
                    pb[i] = __ldg(prow + i * HW);
                    tb[i] = __ldg(trow + i * HW);
                }
            }
        }

#pragma unroll
        for (int rr = 0; rr < 26; rr++) {
            float p = pb[rr & 3];
            float t = tb[rr & 3];
            if (rr + 4 < 26) {
                int rn = rr + 4;
                if (INTERIOR) {
                    pb[rr & 3] = __ldg(prow + rn * HW);
                    tb[rr & 3] = __ldg(trow + rn * HW);
                } else {
                    int gy = gybase + rn;
                    float pv = 0.f, tv = 0.f;
                    if (xok && gy >= 0 && gy < HW) {
                        pv = __ldg(prow + rn * HW);
                        tv = __ldg(trow + rn * HW);
                    }
                    pb[rr & 3] = pv; tb[rr & 3] = tv;
                }
            }

            float sv = p + t;
            float dv = p - t;
            ull pt = f2pack(p, t);
            ull sd = f2pack(sv * sv, dv * dv);
#pragma unroll
            for (int j = 0; j < 16; j++) {
                int k = rr - j;
                if (k >= 0 && k <= 10) {
                    int slot = j % 11;
                    a01[slot] = fma2(Wb[k], pt, a01[slot]);
                    a23[slot] = fma2(Wb[k], sd, a23[slot]);
                }
            }
            if (rr >= 10) {
                int j = rr - 10;
                int slot = j % 11;
                hb01[j * HBW2 + c] = a01[slot];  a01[slot] = 0ull;
                hb23[j * HBW2 + c] = a23[slot];  a23[slot] = 0ull;
            }
        }
    }
}

__global__ __launch_bounds__(256, 2) void ssim_main_kernel(
    const float* __restrict__ pred,
    const float* __restrict__ target,
    float* __restrict__ out,
    float inv_count)
{
    extern __shared__ __align__(16) ull smem_raw[];
    ull* hb01 = smem_raw;                   // [16][268] u64 = 34304 B
    ull* hb23 = smem_raw + TH * HBW2;       // [16][268] u64 = 34304 B
    __shared__ float red[8];
    __shared__ bool s_last;

    const int tid = threadIdx.x;
    const int x0 = blockIdx.x * TW;
    const int y0 = blockIdx.y * TH;
    const size_t plane_off = (size_t)blockIdx.z * PLANE_ELEMS;
    const float* __restrict__ pp = pred + plane_off;
    const float* __restrict__ tt = target + plane_off;

    // Broadcast weight pairs {W[k], W[k]}.
    ull Wb[11];
    Wb[0]  = f2pack(W0, W0);  Wb[1]  = f2pack(W1, W1);
    Wb[2]  = f2pack(W2, W2);  Wb[3]  = f2pack(W3, W3);
    Wb[4]  = f2pack(W4, W4);  Wb[5]  = f2pack(W5, W5);
    Wb[6]  = Wb[4]; Wb[7] = Wb[3]; Wb[8] = Wb[2]; Wb[9] = Wb[1]; Wb[10] = Wb[0];

    // ---- Phase V ----
    const bool interior =
        (x0 >= RAD) && (x0 + TW + RAD <= HW) && (y0 >= RAD) && (y0 + TH + RAD <= HW);
    if (interior) ssim_phase_v<true >(pp, tt, x0, y0, tid, hb01, hb23, Wb);
    else          ssim_phase_v<false>(pp, tt, x0, y0, tid, hb01, hb23, Wb);
    __syncthreads();

    // ---- Phase H: 4 quads/thread; quad = 4 consecutive x in one row ----
    const float C1 = 0.0001f;
    const float C2 = 0.0009f;
    float local = 0.f;

#pragma unroll
    for (int it = 0; it < 4; it++) {
        int h = tid + 256 * it;          // 0..1023
        int r = h >> 6;                  // row 0..15
        int cg = (h & 63) << 2;          // x base 0..252
        const ull* rb01 = hb01 + r * HBW2 + cg;
        const ull* rb23 = hb23 + r * HBW2 + cg;

        float mu1[4], mu2[4], css[4], cdd[4];
        {
            ull v[16];
#pragma unroll
            for (int q = 0; q < 8; q++) {
                ulonglong2 u = *(const ulonglong2*)(rb01 + 2 * q);
                v[2 * q] = u.x; v[2 * q + 1] = u.y;
            }
            ull acc[4] = {0ull, 0ull, 0ull, 0ull};
#pragma unroll
            for (int i = 0; i < 14; i++) {
#pragma unroll
                for (int j = 0; j < 4; j++) {
                    int k = i - j;
                    if (k >= 0 && k <= 10)
                        acc[j] = fma2(Wb[k], v[i], acc[j]);
                }
            }
#pragma unroll
            for (int j = 0; j < 4; j++) f2unpack(mu1[j], mu2[j], acc[j]);
        }
        {
            ull v[16];
#pragma unroll
            for (int q = 0; q < 8; q++) {
                ulonglong2 u = *(const ulonglong2*)(rb23 + 2 * q);
                v[2 * q] = u.x; v[2 * q + 1] = u.y;
            }
            ull acc[4] = {0ull, 0ull, 0ull, 0ull};
#pragma unroll
            for (int i = 0; i < 14; i++) {
#pragma unroll
                for (int j = 0; j < 4; j++) {
                    int k = i - j;
                    if (k >= 0 && k <= 10)
                        acc[j] = fma2(Wb[k], v[i], acc[j]);
                }
            }
#pragma unroll
            for (int j = 0; j < 4; j++) f2unpack(css[j], cdd[j], acc[j]);
        }

#pragma unroll
        for (int j = 0; j < 4; j++) {
            float m1 = mu1[j], m2 = mu2[j];
            float m1s = m1 * m1;
            float m2s = m2 * m2;
            float m12 = m1 * m2;
            float ept   = 0.25f * (css[j] - cdd[j]);
            float epptt = 0.5f  * (css[j] + cdd[j]);
            float s12  = ept - m12;
            float ssum = epptt - m1s - m2s;
            float num = (2.0f * m12 + C1) * (2.0f * s12 + C2);
            float den = (m1s + m2s + C1) * (ssum + C2);
            local += __fdividef(num, den);
        }
    }

    // ---- Block reduction -> partial; last block reduces globally ----
#pragma unroll
    for (int off = 16; off > 0; off >>= 1)
        local += __shfl_down_sync(0xffffffffu, local, off);
    if ((tid & 31) == 0) red[tid >> 5] = local;
    __syncthreads();
    if (tid == 0) {
        float v = red[0] + red[1] + red[2] + red[3]
                + red[4] + red[5] + red[6] + red[7];
        int bid = (blockIdx.z * gridDim.y + blockIdx.y) * gridDim.x + blockIdx.x;
        g_partials[bid] = v;
        __threadfence();
        unsigned int n = atomicAdd(&g_counter, 1u);
        s_last = (n == NBLOCKS - 1u);
    }
    __syncthreads();

    if (s_last) {
        __threadfence();
        __shared__ double dred[8];
        const float4* __restrict__ p4 = (const float4*)g_partials;
        double acc = 0.0;
#pragma unroll
        for (int i = 0; i < NBLOCKS / 4 / 256; i++) {
            float4 v = p4[i * 256 + tid];
            acc += (double)v.x + (double)v.y + (double)v.z + (double)v.w;
        }
#pragma unroll
        for (int off = 16; off > 0; off >>= 1)
            acc += __shfl_down_sync(0xffffffffu, acc, off);
        if ((tid & 31) == 0) dred[tid >> 5] = acc;
        __syncthreads();
        if (tid == 0) {
            double s = dred[0] + dred[1] + dred[2] + dred[3]
                     + dred[4] + dred[5] + dred[6] + dred[7];
            out[0] = 1.0f - (float)(s * (double)inv_count);
            g_counter = 0;
        }
    }
}

extern "C" void kernel_launch(void* const* d_in, const int* in_sizes, int n_in,
                              void* d_out, int out_size) {
    const float* pred = (const float*)d_in[0];
    const float* target = (const float*)d_in[1];
    float* out = (float*)d_out;

    const int total = in_sizes[0];                 // N*C*H*W
    const int nplanes = total / PLANE_ELEMS;       // 48

    const size_t smem = sizeof(ull) * 2 * TH * HBW2;   // 68608 B
    cudaFuncSetAttribute(ssim_main_kernel,
                         cudaFuncAttributeMaxDynamicSharedMemorySize, (int)smem);

    dim3 grid(HW / TW, HW / TH, nplanes);          // (2, 32, 48) = 3072 blocks
    ssim_main_kernel<<<grid, 256, smem>>>(pred, target, out, 1.0f / (float)total);
}